// round 4
// baseline (speedup 1.0000x reference)
#include <cuda_runtime.h>
#include <cuda_bf16.h>
#include <cstddef>

// LIF activation over time axis.
// x: [B=64, T=500, C=1024] fp32; w_input, w_leak: device scalars.
// out: spikes [B, T, C] fp32 (0.0/1.0).
//
// R3 -> R4: ptxas sinks loads to their uses within a loop body (regs=32 in
// all prior rounds => MLP_eff ~3). Fix structurally: software-pipelined
// ping-pong buffers. Loads issued in iteration i are consumed in iteration
// i+1 (across the loop back-edge), so ptxas CANNOT sink them -> 10 loads
// genuinely in flight per warp while the recurrence chain runs.
// Also shortened the per-step dependent chain: Vm>=0 so
// step(1-Vm)*Vm == (Vm<1 ? Vm : 0)  (FSEL+FFMA+FMAX = ~12cyc/step).

#define LIF_B 64
#define LIF_T 500
#define LIF_C 1024
#define LIF_U 10          // prefetch batch depth
#define LIF_BLOCK 64

__global__ __launch_bounds__(LIF_BLOCK) void lif_kernel(
    const float* __restrict__ x,
    const float* __restrict__ w_input_p,
    const float* __restrict__ w_leak_p,
    float* __restrict__ out)
{
    const int tid = blockIdx.x * blockDim.x + threadIdx.x;  // 0 .. B*C-1
    const float wi   = *w_input_p;
    const float keep = 1.0f - *w_leak_p;

    const int b = tid >> 10;        // / C
    const int c = tid & (LIF_C - 1);

    const size_t base = (size_t)b * LIF_T * LIF_C + c;
    const float* xp = x + base;
    float* op = out + base;

    float Vm = 0.0f;
    float bufA[LIF_U], bufB[LIF_U];

    // Prologue: load batch 0 into A.
    #pragma unroll
    for (int i = 0; i < LIF_U; i++)
        bufA[i] = xp[(size_t)i * LIF_C];

    // 500 = 25 * (2*LIF_U). Each iteration handles two batches (A then B),
    // always prefetching one batch ahead into the idle buffer.
    #pragma unroll 1
    for (int t0 = 0; t0 < LIF_T; t0 += 2 * LIF_U) {
        // Prefetch batch t0+U into B (consumer is below -> overlaps nothing
        // it can sink into; issues before the A-chain stalls the warp).
        {
            const size_t tb = (size_t)(t0 + LIF_U);
            #pragma unroll
            for (int i = 0; i < LIF_U; i++)
                bufB[i] = xp[(tb + i) * LIF_C];
        }

        // Compute batch A (times t0 .. t0+U-1).
        #pragma unroll
        for (int i = 0; i < LIF_U; i++) {
            const float wx = wi * bufA[i];                  // off critical chain
            const float vk = (Vm < 1.0f) ? Vm : 0.0f;       // Vm * forget
            Vm = fmaxf(fmaf(keep, vk, wx), 0.0f);
            op[(size_t)(t0 + i) * LIF_C] = (Vm > 1.0f) ? 1.0f : 0.0f;
        }

        // Prefetch batch t0+2U into A. On the last iteration this would be
        // out of range; clamp to a valid batch (result unused).
        {
            int tn = t0 + 2 * LIF_U;
            if (tn > LIF_T - LIF_U) tn = LIF_T - LIF_U;
            const size_t ta = (size_t)tn;
            #pragma unroll
            for (int i = 0; i < LIF_U; i++)
                bufA[i] = xp[(ta + i) * LIF_C];
        }

        // Compute batch B (times t0+U .. t0+2U-1).
        #pragma unroll
        for (int i = 0; i < LIF_U; i++) {
            const float wx = wi * bufB[i];
            const float vk = (Vm < 1.0f) ? Vm : 0.0f;
            Vm = fmaxf(fmaf(keep, vk, wx), 0.0f);
            op[(size_t)(t0 + LIF_U + i) * LIF_C] = (Vm > 1.0f) ? 1.0f : 0.0f;
        }
    }
}

extern "C" void kernel_launch(void* const* d_in, const int* in_sizes, int n_in,
                              void* d_out, int out_size) {
    const float* x        = (const float*)d_in[0];
    const float* w_input  = (const float*)d_in[1];
    const float* w_leak   = (const float*)d_in[2];
    float* out            = (float*)d_out;

    const int lanes = LIF_B * LIF_C;  // 65536
    lif_kernel<<<lanes / LIF_BLOCK, LIF_BLOCK>>>(x, w_input, w_leak, out);
}

// round 5
// speedup vs baseline: 1.3895x; 1.3895x over previous
#include <cuda_runtime.h>
#include <cuda_bf16.h>
#include <cstddef>
#include <cstdint>

// LIF activation over time axis.
// x: [B=64, T=500, C=1024] fp32; w_input, w_leak: device scalars.
// out: spikes [B, T, C] fp32 (0.0/1.0).
//
// R4 -> R5: ptxas provably refuses to keep >~6 LDG destination registers
// live (regs=32 in every prior round; MLP_eff 3-6; DRAM <= 50%). Switch the
// input stream to cp.async (LDGSTS): fire-and-forget into smem, NO
// destination register, so the 25-deep prefetch cannot be sunk or collapsed.
// Double-buffered 25-timestep stages; each thread copies and reads only its
// own smem column -> per-thread cp.async group semantics, no __syncthreads.
// Sustained in-flight: 2048 warps * 25 * 128B = 6.5MB (~2.5x BW*latency).

#define LIF_B 64
#define LIF_T 500
#define LIF_C 1024
#define LIF_D 25                 // timesteps per stage
#define LIF_BLOCK 64
#define LIF_NCHUNK (LIF_T / LIF_D)   // 20

__global__ __launch_bounds__(LIF_BLOCK) void lif_kernel(
    const float* __restrict__ x,
    const float* __restrict__ w_input_p,
    const float* __restrict__ w_leak_p,
    float* __restrict__ out)
{
    __shared__ float sbuf[2][LIF_D][LIF_BLOCK];   // 12.8 KB

    const int tidb = threadIdx.x;
    const int tid  = blockIdx.x * LIF_BLOCK + tidb;   // 0 .. B*C-1
    const float wi   = *w_input_p;
    const float keep = 1.0f - *w_leak_p;

    const int b = tid >> 10;          // / C
    const int c = tid & (LIF_C - 1);

    const size_t base = (size_t)b * LIF_T * LIF_C + c;
    const float* xp = x + base;
    float* op = out + base;

    // Prologue: stage 0 <- chunk 0.
    #pragma unroll
    for (int i = 0; i < LIF_D; i++) {
        uint32_t dst = (uint32_t)__cvta_generic_to_shared(&sbuf[0][i][tidb]);
        const float* src = xp + (size_t)i * LIF_C;
        asm volatile("cp.async.ca.shared.global [%0], [%1], 4;"
                     :: "r"(dst), "l"(src) : "memory");
    }
    asm volatile("cp.async.commit_group;" ::: "memory");

    float Vm = 0.0f;

    #pragma unroll 1
    for (int k = 0; k < LIF_NCHUNK; k++) {
        // Prefetch chunk k+1 into the other stage. On the last iteration
        // clamp to chunk k (dead copies, L2-hot) to keep group counts uniform.
        const int kn = (k + 1 < LIF_NCHUNK) ? (k + 1) : k;
        const int sN = (k + 1) & 1;
        const float* srcbase = xp + (size_t)kn * LIF_D * LIF_C;
        #pragma unroll
        for (int i = 0; i < LIF_D; i++) {
            uint32_t dst = (uint32_t)__cvta_generic_to_shared(&sbuf[sN][i][tidb]);
            asm volatile("cp.async.ca.shared.global [%0], [%1], 4;"
                         :: "r"(dst), "l"(srcbase + (size_t)i * LIF_C) : "memory");
        }
        asm volatile("cp.async.commit_group;" ::: "memory");

        // Wait until only the newest group is pending -> chunk k is resident.
        asm volatile("cp.async.wait_group 1;" ::: "memory");

        // Compute chunk k from smem (own column only).
        const int s = k & 1;
        const size_t ob = (size_t)k * LIF_D * LIF_C;
        #pragma unroll
        for (int i = 0; i < LIF_D; i++) {
            const float xv = sbuf[s][i][tidb];
            const float wx = wi * xv;                     // off critical chain
            const float vk = (Vm < 1.0f) ? Vm : 0.0f;     // Vm * step(1-Vm)
            Vm = fmaxf(fmaf(keep, vk, wx), 0.0f);
            op[ob + (size_t)i * LIF_C] = (Vm > 1.0f) ? 1.0f : 0.0f;
        }
    }
}

extern "C" void kernel_launch(void* const* d_in, const int* in_sizes, int n_in,
                              void* d_out, int out_size) {
    const float* x        = (const float*)d_in[0];
    const float* w_input  = (const float*)d_in[1];
    const float* w_leak   = (const float*)d_in[2];
    float* out            = (float*)d_out;

    const int lanes = LIF_B * LIF_C;  // 65536
    lif_kernel<<<lanes / LIF_BLOCK, LIF_BLOCK>>>(x, w_input, w_leak, out);
}

// round 6
// speedup vs baseline: 1.4697x; 1.0577x over previous
#include <cuda_runtime.h>
#include <cuda_bf16.h>
#include <cstddef>
#include <cstdint>

// LIF activation over time axis.
// x: [B=64, T=500, C=1024] fp32; w_input, w_leak: device scalars.
// out: spikes [B, T, C] fp32 (0.0/1.0).
//
// R5 -> R6: cp.async fixed the load-sinking (R5 win) but DRAM stuck at 54%:
// with 2 stages / wait_group 1, each warp had only ONE 25-line group in
// flight while waiting. This round:
//  * 4 smem stages + wait_group 2 -> 2-3 groups (50-75 LDGSTS) continuously
//    in flight per warp (LDGSTS has no depth cap, unlike LDG's ~55)
//  * float2 per thread (2 channels) -> 8B cp.async = 256B/warp-instr,
//    half the issue cost, half the request count per byte, 2 independent
//    Vm chains (ILP), 8B stores.
// Sustained in-flight ~16MB chip-wide vs ~2.6MB needed.

#define LIF_B 64
#define LIF_T 500
#define LIF_C 1024
#define LIF_D 25                     // timesteps per stage
#define LIF_STAGES 4
#define LIF_BLOCK 32
#define LIF_NCHUNK (LIF_T / LIF_D)   // 20
#define LIF_PAIRS (LIF_C / 2)        // 512 float2 lanes per batch row

__global__ __launch_bounds__(LIF_BLOCK) void lif_kernel(
    const float* __restrict__ x,
    const float* __restrict__ w_input_p,
    const float* __restrict__ w_leak_p,
    float* __restrict__ out)
{
    __shared__ float2 sbuf[LIF_STAGES][LIF_D][LIF_BLOCK];   // 25.6 KB

    const int tidb = threadIdx.x;
    const int g    = blockIdx.x * LIF_BLOCK + tidb;   // 0 .. B*C/2-1
    const float wi   = *w_input_p;
    const float keep = 1.0f - *w_leak_p;

    const int b  = g / LIF_PAIRS;
    const int cp = g - b * LIF_PAIRS;

    const size_t base = (size_t)b * LIF_T * LIF_C + (size_t)cp * 2;
    const float* xp = x + base;          // 8B aligned
    float* op = out + base;

    // Prologue: issue chunks 0,1,2 (3 groups pending).
    #pragma unroll
    for (int k = 0; k < LIF_STAGES - 1; k++) {
        const float* src = xp + (size_t)k * LIF_D * LIF_C;
        #pragma unroll
        for (int i = 0; i < LIF_D; i++) {
            uint32_t dst = (uint32_t)__cvta_generic_to_shared(&sbuf[k][i][tidb]);
            asm volatile("cp.async.ca.shared.global [%0], [%1], 8;"
                         :: "r"(dst), "l"(src + (size_t)i * LIF_C) : "memory");
        }
        asm volatile("cp.async.commit_group;" ::: "memory");
    }

    float Vm0 = 0.0f, Vm1 = 0.0f;

    #pragma unroll 1
    for (int k = 0; k < LIF_NCHUNK; k++) {
        // Chunk k's group is the oldest of the 3 pending; let 2 stay in flight.
        asm volatile("cp.async.wait_group %0;" :: "n"(LIF_STAGES - 2) : "memory");

        // Issue chunk k+3 into stage (k+3)%4 BEFORE computing, so the new
        // group overlaps the compute chain. Clamp at the end (dead, L2-hot).
        {
            int kn = k + LIF_STAGES - 1;
            if (kn >= LIF_NCHUNK) kn = LIF_NCHUNK - 1;
            const int sN = (k + LIF_STAGES - 1) & (LIF_STAGES - 1);
            const float* src = xp + (size_t)kn * LIF_D * LIF_C;
            #pragma unroll
            for (int i = 0; i < LIF_D; i++) {
                uint32_t dst = (uint32_t)__cvta_generic_to_shared(&sbuf[sN][i][tidb]);
                asm volatile("cp.async.ca.shared.global [%0], [%1], 8;"
                             :: "r"(dst), "l"(src + (size_t)i * LIF_C) : "memory");
            }
            asm volatile("cp.async.commit_group;" ::: "memory");
        }

        // Compute chunk k from smem: two independent recurrences.
        const int s = k & (LIF_STAGES - 1);
        const size_t ob = (size_t)k * LIF_D * LIF_C;
        #pragma unroll
        for (int i = 0; i < LIF_D; i++) {
            const float2 xv = sbuf[s][i][tidb];
            const float wx0 = wi * xv.x;
            const float wx1 = wi * xv.y;
            const float vk0 = (Vm0 < 1.0f) ? Vm0 : 0.0f;   // Vm * step(1-Vm)
            const float vk1 = (Vm1 < 1.0f) ? Vm1 : 0.0f;
            Vm0 = fmaxf(fmaf(keep, vk0, wx0), 0.0f);
            Vm1 = fmaxf(fmaf(keep, vk1, wx1), 0.0f);
            float2 sp;
            sp.x = (Vm0 > 1.0f) ? 1.0f : 0.0f;
            sp.y = (Vm1 > 1.0f) ? 1.0f : 0.0f;
            *reinterpret_cast<float2*>(op + ob + (size_t)i * LIF_C) = sp;
        }
    }
}

extern "C" void kernel_launch(void* const* d_in, const int* in_sizes, int n_in,
                              void* d_out, int out_size) {
    const float* x        = (const float*)d_in[0];
    const float* w_input  = (const float*)d_in[1];
    const float* w_leak   = (const float*)d_in[2];
    float* out            = (float*)d_out;

    const int lanes = LIF_B * LIF_C / 2;  // 32768 float2 lanes
    lif_kernel<<<lanes / LIF_BLOCK, LIF_BLOCK>>>(x, w_input, w_leak, out);
}

// round 7
// speedup vs baseline: 1.7122x; 1.1650x over previous
#include <cuda_runtime.h>
#include <cuda_bf16.h>
#include <cstddef>
#include <cstdint>

// LIF activation over time axis.
// x: [B=64, T=500, C=1024] fp32; w_input, w_leak: device scalars.
// out: spikes [B, T, C] fp32 (0.0/1.0).
//
// R6 -> R7: R5/R6 showed DRAM pinned at 54-58% regardless of program-side
// MLP (1 vs 3 groups in flight, 4B vs 8B ops) => per-SM cap on outstanding
// L1tex fill requests. Fix: fill smem via cp.async.bulk (TMA / UBLKCP),
// whose completion tracking lives in the TMA engine, not the L1tex queue.
//
// Layout: block = (batch, half-row) -> 512 channels, 2KB contiguous per
// timestep => 1D bulk copies, no tensormap. grid=128, block=160:
// 128 compute threads (float4 each, 4 Vm chains) + 1 producer warp.
// 5-stage mbarrier pipeline, 10 timesteps (20KB) per stage, 100KB dyn smem.

#define LIF_B 64
#define LIF_T 500
#define LIF_C 1024
#define LIF_HALF 512                     // channels per block
#define LIF_D 10                         // timesteps per stage
#define LIF_NS 5                         // pipeline stages
#define LIF_NCHUNK (LIF_T / LIF_D)       // 50
#define ROW_BYTES (LIF_HALF * 4)         // 2048
#define STAGE_BYTES (LIF_D * ROW_BYTES)  // 20480
#define SMEM_BYTES (LIF_NS * STAGE_BYTES)
#define NTHREADS 160

__device__ __forceinline__ uint32_t smem_u32(const void* p) {
    return (uint32_t)__cvta_generic_to_shared(p);
}

__device__ __forceinline__ void mbar_init(uint32_t bar, uint32_t count) {
    asm volatile("mbarrier.init.shared.b64 [%0], %1;" :: "r"(bar), "r"(count) : "memory");
}
__device__ __forceinline__ void mbar_arrive(uint32_t bar) {
    asm volatile("mbarrier.arrive.shared.b64 _, [%0];" :: "r"(bar) : "memory");
}
__device__ __forceinline__ void mbar_expect_tx(uint32_t bar, uint32_t bytes) {
    asm volatile("mbarrier.arrive.expect_tx.shared.b64 _, [%0], %1;"
                 :: "r"(bar), "r"(bytes) : "memory");
}
__device__ __forceinline__ void mbar_wait(uint32_t bar, uint32_t parity) {
    asm volatile(
        "{\n\t"
        ".reg .pred P;\n\t"
        "WAIT_%=:\n\t"
        "mbarrier.try_wait.parity.acquire.cta.shared::cta.b64 P, [%0], %1, 0x989680;\n\t"
        "@!P bra WAIT_%=;\n\t"
        "}"
        :: "r"(bar), "r"(parity) : "memory");
}
__device__ __forceinline__ void bulk_g2s(uint32_t dst, const void* src,
                                         uint32_t bytes, uint32_t bar) {
    asm volatile(
        "cp.async.bulk.shared::cta.global.mbarrier::complete_tx::bytes [%0], [%1], %2, [%3];"
        :: "r"(dst), "l"(src), "r"(bytes), "r"(bar) : "memory");
}

__global__ __launch_bounds__(NTHREADS) void lif_kernel(
    const float* __restrict__ x,
    const float* __restrict__ w_input_p,
    const float* __restrict__ w_leak_p,
    float* __restrict__ out)
{
    extern __shared__ float sdata[];                    // LIF_NS stages of [D][512] floats
    __shared__ __align__(8) uint64_t mbar[2 * LIF_NS];  // full[0..NS), empty[0..NS)

    const int tid = threadIdx.x;
    const uint32_t sbase = smem_u32(sdata);
    const uint32_t full0  = smem_u32(&mbar[0]);
    const uint32_t empty0 = smem_u32(&mbar[LIF_NS]);

    if (tid == 0) {
        #pragma unroll
        for (int s = 0; s < LIF_NS; s++) {
            mbar_init(full0  + 8u * s, 1);    // producer's expect_tx arrival
            mbar_init(empty0 + 8u * s, 128);  // all compute threads arrive
        }
    }
    __syncthreads();

    const int blk  = blockIdx.x;       // 0..127
    const int b    = blk >> 1;
    const int half = blk & 1;
    const size_t gbase = (size_t)b * LIF_T * LIF_C + (size_t)half * LIF_HALF;  // floats

    if (tid >= 128) {
        // ---------------- producer warp ----------------
        if (tid != 128) return;        // one thread drives TMA
        const char* src0 = (const char*)(x + gbase);
        int ph = 1;                    // empty barriers: first pass must not block
        #pragma unroll 1
        for (int k = 0; k < LIF_NCHUNK; k++) {
            const int s = k % LIF_NS;
            mbar_wait(empty0 + 8u * s, (uint32_t)ph);
            mbar_expect_tx(full0 + 8u * s, STAGE_BYTES);
            const char* src = src0 + (size_t)k * LIF_D * LIF_C * 4;
            #pragma unroll
            for (int j = 0; j < LIF_D; j++)
                bulk_g2s(sbase + (uint32_t)(s * LIF_D + j) * ROW_BYTES,
                         src + (size_t)j * LIF_C * 4,
                         ROW_BYTES, full0 + 8u * s);
            if (s == LIF_NS - 1) ph ^= 1;
        }
        return;
    }

    // ---------------- compute threads (128, float4 each) ----------------
    const float wi   = *w_input_p;
    const float keep = 1.0f - *w_leak_p;

    float* orow = out + gbase;         // + t*C + tid*4 per step
    float Vm0 = 0.0f, Vm1 = 0.0f, Vm2 = 0.0f, Vm3 = 0.0f;
    int ph = 0;

    #pragma unroll 1
    for (int k = 0; k < LIF_NCHUNK; k++) {
        const int s = k % LIF_NS;
        mbar_wait(full0 + 8u * s, (uint32_t)ph);

        const float4* srow = (const float4*)(sdata + (size_t)s * LIF_D * LIF_HALF) + tid;
        #pragma unroll
        for (int j = 0; j < LIF_D; j++) {
            const float4 xv = srow[(size_t)j * (LIF_HALF / 4)];
            const float vk0 = (Vm0 < 1.0f) ? Vm0 : 0.0f;   // Vm * step(1-Vm)
            const float vk1 = (Vm1 < 1.0f) ? Vm1 : 0.0f;
            const float vk2 = (Vm2 < 1.0f) ? Vm2 : 0.0f;
            const float vk3 = (Vm3 < 1.0f) ? Vm3 : 0.0f;
            Vm0 = fmaxf(fmaf(keep, vk0, wi * xv.x), 0.0f);
            Vm1 = fmaxf(fmaf(keep, vk1, wi * xv.y), 0.0f);
            Vm2 = fmaxf(fmaf(keep, vk2, wi * xv.z), 0.0f);
            Vm3 = fmaxf(fmaf(keep, vk3, wi * xv.w), 0.0f);
            float4 sp;
            sp.x = (Vm0 > 1.0f) ? 1.0f : 0.0f;
            sp.y = (Vm1 > 1.0f) ? 1.0f : 0.0f;
            sp.z = (Vm2 > 1.0f) ? 1.0f : 0.0f;
            sp.w = (Vm3 > 1.0f) ? 1.0f : 0.0f;
            *(float4*)(orow + (size_t)(k * LIF_D + j) * LIF_C + tid * 4) = sp;
        }

        mbar_arrive(empty0 + 8u * s);
        if (s == LIF_NS - 1) ph ^= 1;
    }
}

extern "C" void kernel_launch(void* const* d_in, const int* in_sizes, int n_in,
                              void* d_out, int out_size) {
    const float* x        = (const float*)d_in[0];
    const float* w_input  = (const float*)d_in[1];
    const float* w_leak   = (const float*)d_in[2];
    float* out            = (float*)d_out;

    cudaFuncSetAttribute(lif_kernel,
                         cudaFuncAttributeMaxDynamicSharedMemorySize, SMEM_BYTES);

    lif_kernel<<<LIF_B * 2, NTHREADS, SMEM_BYTES>>>(x, w_input, w_leak, out);
}